// round 15
// baseline (speedup 1.0000x reference)
#include <cuda_runtime.h>
#include <math.h>

#define NQ 300
#define NF 8
#define BS 2
#define HW 96
#define HWHW 9216
#define D_TOT 73728.0f   // NF*H*W
#define L2E 1.4426950408889634f
#define LN2 0.6931471805599453f

typedef unsigned long long u64;

__device__ __forceinline__ float ex2_approx(float x) {
    float y; asm("ex2.approx.ftz.f32 %0, %1;" : "=f"(y) : "f"(x)); return y;
}
__device__ __forceinline__ float lg2_approx(float x) {
    float y; asm("lg2.approx.ftz.f32 %0, %1;" : "=f"(y) : "f"(x)); return y;
}
__device__ __forceinline__ float rcp_approx(float x) {
    float y; asm("rcp.approx.ftz.f32 %0, %1;" : "=f"(y) : "f"(x)); return y;
}
__device__ __forceinline__ u64 mul2(u64 a, u64 b) {
    u64 r; asm("mul.rn.f32x2 %0, %1, %2;" : "=l"(r) : "l"(a), "l"(b)); return r;
}
__device__ __forceinline__ u64 add2(u64 a, u64 b) {
    u64 r; asm("add.rn.f32x2 %0, %1, %2;" : "=l"(r) : "l"(a), "l"(b)); return r;
}
__device__ __forceinline__ u64 fma2(u64 a, u64 b, u64 c) {
    u64 r; asm("fma.rn.f32x2 %0, %1, %2, %3;" : "=l"(r) : "l"(a), "l"(b), "l"(c)); return r;
}
__device__ __forceinline__ void upk(float& a, float& b, u64 p) {
    asm("mov.b64 {%0,%1}, %2;" : "=f"(a), "=f"(b) : "l"(p));
}
__device__ __forceinline__ u64 pk(float a, float b) {
    u64 r; asm("mov.b64 %0, {%1,%2};" : "=l"(r) : "f"(a), "f"(b)); return r;
}
#define ONE2 0x3f8000003f800000ULL

// Scratch (static __device__ — no allocation)
__device__ float g_focal [BS*NF*NQ];
__device__ float g_ssum  [BS*NF*NQ];
__device__ float g_stsum [BS*NF*NQ];
__device__ float g_colmax[BS*NF*NQ*HW];
__device__ float g_rowmax[BS*NF*NQ*HW];
__device__ float g_tcolmax[BS*NF*HW];
__device__ float g_trowmax[BS*NF*HW];
__device__ float g_tsum  [BS*NF];
__device__ float g_S[BS*NF*HWHW];        // per (bf,pixel): t ? -log2e : +log2e
__device__ float g_V[BS*HWHW];           // per (b,pixel): vpad ? 0 : 1
__device__ u64      g_amin[BS];          // packed (ordered-float<<32 | q)
__device__ unsigned g_cnt;

// ---------------------------------------------------------------------------
// Prep (merged): blocks 0..BS*NF-1: fill S + target row/col maxes + tsum.
//                blocks BS*NF..: fill V from vpad; reset argmin scratch.
// ---------------------------------------------------------------------------
__global__ __launch_bounds__(256) void prep_all(
    const float* __restrict__ tmask, const unsigned char* __restrict__ vpad)
{
    if (blockIdx.x < BS*NF) {
        const int bf = blockIdx.x;
        const float* __restrict__ T = tmask + (size_t)bf * HWHW;
        for (int i = threadIdx.x; i < HWHW; i += 256)
            g_S[(size_t)bf*HWHW + i] = (T[i] != 0.f) ? -L2E : L2E;

        const int i = threadIdx.x;
        if (i < HW) {
            float cmax = -1e30f, rmax = -1e30f, rs = 0.f;
            for (int h = 0; h < HW; h++) cmax = fmaxf(cmax, T[h*HW + i]);
            for (int w = 0; w < HW; w++) { float v = T[i*HW + w]; rmax = fmaxf(rmax, v); rs += v; }
            g_tcolmax[bf*HW + i] = cmax;
            g_trowmax[bf*HW + i] = rmax;

            __shared__ float sred[3];
            const int lane = i & 31, warp = i >> 5;
            #pragma unroll
            for (int off = 16; off; off >>= 1) rs += __shfl_xor_sync(0xffffffffu, rs, off);
            if (lane == 0) sred[warp] = rs;
            __syncthreads();
            if (i == 0) g_tsum[bf] = sred[0] + sred[1] + sred[2];
        }
    } else {
        const int b = blockIdx.x - BS*NF;
        const unsigned char* __restrict__ VP = vpad + (size_t)b * HWHW;
        for (int i = threadIdx.x; i < HWHW; i += 256)
            g_V[(size_t)b*HWHW + i] = VP[i] ? 0.f : 1.f;
        if (threadIdx.x == 0) {
            g_amin[b] = 0xFFFFFFFFFFFFFFFFULL;
            if (b == 0) g_cnt = 0u;
        }
    }
}

// ---------------------------------------------------------------------------
// Heavy kernel: one block (192 thr) per (b,f,q) tile. f32x2-packed math.
// Per element: zl = x*V*S (S=±log2e); e=2^zl; sg=e/(1+e); G=log2(1+e)*sg^2
// Recover: focal = ln2*(0.5*f0 + 0.25*ln2*f1)
//          sum(sigmoid)=tsum+ln2*A2 ;  sum(sigmoid*t)=tsum-0.5*(A-ln2*A2)
// ---------------------------------------------------------------------------
__device__ __forceinline__ void pair_step(
    u64 xp, u64 sp, u64 vp,
    u64& f0p, u64& f1p, u64& Ap, u64& A2p,
    float& rm, float& cma, float& cmb)
{
    const u64 xv = mul2(xp, vp);
    const u64 zl = mul2(xv, sp);
    float z0, z1; upk(z0, z1, zl);
    const u64 e2  = pk(ex2_approx(z0), ex2_approx(z1));
    const u64 ope = add2(e2, ONE2);
    float o0, o1; upk(o0, o1, ope);
    const u64 u2 = pk(rcp_approx(o0), rcp_approx(o1));
    const u64 l2 = pk(lg2_approx(o0), lg2_approx(o1));
    const u64 sg = mul2(e2, u2);
    const u64 G  = mul2(mul2(l2, sg), sg);
    f0p = add2(f0p, G);
    f1p = fma2(sp, G, f1p);
    Ap  = add2(Ap, sg);
    A2p = fma2(sp, sg, A2p);
    float xv0, xv1; upk(xv0, xv1, xv);
    rm  = fmaxf(rm, fmaxf(xv0, xv1));
    cma = fmaxf(cma, xv0);
    cmb = fmaxf(cmb, xv1);
}

__global__ __launch_bounds__(192) void mask_heavy(const float* __restrict__ masks)
{
    const int blk = blockIdx.x;          // ((b*NF+f)*NQ + q)
    const int bf  = blk / NQ;
    const int b   = bf / NF;
    const ulonglong2* __restrict__ X  = (const ulonglong2*)(masks + (size_t)blk * HWHW);
    const ulonglong2* __restrict__ Sp = (const ulonglong2*)(g_S   + (size_t)bf  * HWHW);
    const ulonglong2* __restrict__ Vp = (const ulonglong2*)(g_V   + (size_t)b   * HWHW);

    const int tid = threadIdx.x;
    const int c4  = tid % 24;   // float4 column
    const int r0  = tid / 24;   // 0..7 row tier

    __shared__ float rowpm[HW][24];
    __shared__ float cmS[8][HW];
    __shared__ float red[6][4];

    u64 f0p = 0, f1p = 0, Ap = 0, A2p = 0;   // 0 == (0.f,0.f)
    float cm0 = -1e30f, cm1 = -1e30f, cm2 = -1e30f, cm3 = -1e30f;

    #pragma unroll 2
    for (int k = 0; k < 12; k++) {
        const int row = r0 + 8*k;
        const int off = row*24 + c4;             // 16B units
        const ulonglong2 x2 = __ldcs(X + off);   // streaming: masks read once
        const ulonglong2 s2 = Sp[off];           // L1/L2-resident
        const ulonglong2 v2 = Vp[off];
        float rm = -1e30f;
        pair_step(x2.x, s2.x, v2.x, f0p, f1p, Ap, A2p, rm, cm0, cm1);
        pair_step(x2.y, s2.y, v2.y, f0p, f1p, Ap, A2p, rm, cm2, cm3);
        rowpm[row][c4] = rm;
    }

    *(float4*)&cmS[r0][4*c4] = make_float4(cm0, cm1, cm2, cm3);

    float f0a, f0b, f1a, f1b, Aa, Ab, A2a, A2b;
    upk(f0a, f0b, f0p); upk(f1a, f1b, f1p);
    upk(Aa, Ab, Ap);    upk(A2a, A2b, A2p);
    float f0 = f0a + f0b, f1 = f1a + f1b, A = Aa + Ab, A2 = A2a + A2b;

    const int lane = tid & 31, warp = tid >> 5;
    #pragma unroll
    for (int off = 16; off; off >>= 1) {
        f0 += __shfl_xor_sync(0xffffffffu, f0, off);
        f1 += __shfl_xor_sync(0xffffffffu, f1, off);
        A  += __shfl_xor_sync(0xffffffffu, A,  off);
        A2 += __shfl_xor_sync(0xffffffffu, A2, off);
    }
    if (lane == 0) { red[warp][0] = f0; red[warp][1] = f1; red[warp][2] = A; red[warp][3] = A2; }
    __syncthreads();

    if (tid == 0) {
        float F0 = 0.f, F1 = 0.f, At = 0.f, A2t = 0.f;
        #pragma unroll
        for (int i = 0; i < 6; i++) {
            F0 += red[i][0]; F1 += red[i][1]; At += red[i][2]; A2t += red[i][3];
        }
        const float ts = g_tsum[bf];
        g_focal[blk] = LN2 * (0.5f*F0 + 0.25f*LN2*F1);
        g_ssum [blk] = ts + LN2*A2t;
        g_stsum[blk] = ts - 0.5f*(At - LN2*A2t);
    }
    if (tid < HW) {
        const float4* rp = (const float4*)rowpm[tid];
        float4 a = rp[0];
        #pragma unroll
        for (int i = 1; i < 6; i++) {
            const float4 v = rp[i];
            a.x = fmaxf(a.x, v.x); a.y = fmaxf(a.y, v.y);
            a.z = fmaxf(a.z, v.z); a.w = fmaxf(a.w, v.w);
        }
        g_rowmax[(size_t)blk*HW + tid] = fmaxf(fmaxf(a.x, a.y), fmaxf(a.z, a.w));
    } else {
        const int col = tid - HW;
        float m = cmS[0][col];
        #pragma unroll
        for (int i = 1; i < 8; i++) m = fmaxf(m, cmS[i][col]);
        g_colmax[(size_t)blk*HW + col] = m;
    }
}

// ---------------------------------------------------------------------------
// Combine: one WARP per (b,q), fused argmin via packed atomicMin.
// grid = 75 blocks x 8 warps = 600 warps exactly.
// ---------------------------------------------------------------------------
__global__ __launch_bounds__(256) void combine_kernel(
    const float* __restrict__ logits, const float* __restrict__ boxes,
    const float* __restrict__ tboxes, const int* __restrict__ tvalid,
    float* __restrict__ out)
{
    const int bq = blockIdx.x * 8 + (threadIdx.x >> 5);
    const int b  = bq / NQ;
    const int q  = bq % NQ;
    const int lane = threadIdx.x & 31;

    float v0 = 0.f, v1 = 0.f, v2 = 0.f, v3 = 0.f, v4 = 0.f, v5 = 0.f;
    #pragma unroll
    for (int j = lane; j < NF*HW; j += 32) {
        const int f = j / HW, k = j % HW;
        const int src  = ((b*NF + f)*NQ + q)*HW + k;
        const int tsrc = (b*NF + f)*HW + k;
        const float ym = g_colmax[src];
        const float ty = g_tcolmax[tsrc];
        const float sy = rcp_approx(1.f + ex2_approx(-L2E*ym));
        v0 += sy; v1 += (ty != 0.f) ? sy : 0.f; v2 += ty;
        const float xm = g_rowmax[src];
        const float tx = g_trowmax[tsrc];
        const float sx = rcp_approx(1.f + ex2_approx(-L2E*xm));
        v3 += sx; v4 += (tx != 0.f) ? sx : 0.f; v5 += tx;
    }

    float cls = 0.f, wv = 0.f, cb = 0.f, cg = 0.f;
    float focal = 0.f, ss = 0.f, st = 0.f, ts = 0.f;
    if (lane < NF) {
        const int f  = lane;
        const int idx = (b*NF + f)*NQ + q;
        focal = g_focal[idx]; ss = g_ssum[idx]; st = g_stsum[idx];
        ts = g_tsum[b*NF + f];

        const float lg = logits[idx];
        const float p  = __fdividef(1.f, 1.f + __expf(-lg));
        const float neg = 0.75f * p * p * (-__logf(1.f - p + 1e-8f));
        const float pos = 0.25f * (1.f - p) * (1.f - p) * (-__logf(p + 1e-8f));
        wv = (tvalid[b*NF + f] != 0) ? 1.f : 0.f;
        cls = wv * (pos - neg);

        const float* sb = boxes  + (size_t)idx * 4;
        const float* tb = tboxes + (size_t)(b*NF + f) * 4;
        cb = fabsf(sb[0]-tb[0]) + fabsf(sb[1]-tb[1])
           + fabsf(sb[2]-tb[2]) + fabsf(sb[3]-tb[3]);

        const float sx0 = sb[0] - 0.5f*sb[2], sy0 = sb[1] - 0.5f*sb[3];
        const float sx1 = sb[0] + 0.5f*sb[2], sy1 = sb[1] + 0.5f*sb[3];
        const float tx0 = tb[0] - 0.5f*tb[2], ty0 = tb[1] - 0.5f*tb[3];
        const float tx1 = tb[0] + 0.5f*tb[2], ty1 = tb[1] + 0.5f*tb[3];
        const float a1 = (sx1 - sx0) * (sy1 - sy0);
        const float a2 = (tx1 - tx0) * (ty1 - ty0);
        float iw = fminf(sx1, tx1) - fmaxf(sx0, tx0); iw = fmaxf(iw, 0.f);
        float ih = fminf(sy1, ty1) - fmaxf(sy0, ty0); ih = fmaxf(ih, 0.f);
        const float inter = iw * ih;
        const float uni = a1 + a2 - inter;
        const float iou = inter / uni;
        float cw = fmaxf(sx1, tx1) - fminf(sx0, tx0); cw = fmaxf(cw, 0.f);
        float ch = fmaxf(sy1, ty1) - fminf(sy0, ty0); ch = fmaxf(ch, 0.f);
        const float areac = cw * ch;
        cg = -(iou - (areac - uni) / areac);
    }

    #pragma unroll
    for (int off = 16; off; off >>= 1) {
        v0 += __shfl_xor_sync(0xffffffffu, v0, off);
        v1 += __shfl_xor_sync(0xffffffffu, v1, off);
        v2 += __shfl_xor_sync(0xffffffffu, v2, off);
        v3 += __shfl_xor_sync(0xffffffffu, v3, off);
        v4 += __shfl_xor_sync(0xffffffffu, v4, off);
        v5 += __shfl_xor_sync(0xffffffffu, v5, off);
        cls += __shfl_xor_sync(0xffffffffu, cls, off);
        wv  += __shfl_xor_sync(0xffffffffu, wv,  off);
        cb  += __shfl_xor_sync(0xffffffffu, cb,  off);
        cg  += __shfl_xor_sync(0xffffffffu, cg,  off);
        focal += __shfl_xor_sync(0xffffffffu, focal, off);
        ss  += __shfl_xor_sync(0xffffffffu, ss,  off);
        st  += __shfl_xor_sync(0xffffffffu, st,  off);
        ts  += __shfl_xor_sync(0xffffffffu, ts,  off);
    }

    if (lane == 0) {
        const float cost_mask = focal / D_TOT;
        const float cost_dice = -(2.f*st + 1.f) / (ss + ts + 1.f);
        const float dice_y = (2.f*v1 + 1.f) / (v0 + v2 + 1.f);
        const float dice_x = (2.f*v4 + 1.f) / (v3 + v5 + 1.f);
        const float cost_proj = -0.5f * (dice_y + dice_x);
        const float c = cls / wv + cb * (1.f/(float)NF) + cg * (1.f/(float)NF)
                      + cost_mask + cost_dice + cost_proj;
        out[bq] = c;

        // fused argmin: total-order key (ordered-float, then q for first-occurrence)
        unsigned ub = __float_as_uint(c);
        ub = (ub & 0x80000000u) ? ~ub : (ub | 0x80000000u);
        const u64 key = ((u64)ub << 32) | (unsigned)q;
        atomicMin(&g_amin[b], key);
        __threadfence();
        const unsigned prev = atomicAdd(&g_cnt, 1u);
        if (prev == BS*NQ - 1) {   // last warp: publish indices
            #pragma unroll
            for (int bb = 0; bb < BS; bb++) {
                const u64 k = atomicMin(&g_amin[bb], 0xFFFFFFFFFFFFFFFFULL); // no-op read
                out[BS*NQ + bb]      = (float)(unsigned)(k & 0xFFFFFFFFu);
                out[BS*NQ + BS + bb] = 0.f;
            }
        }
    }
}

extern "C" void kernel_launch(void* const* d_in, const int* in_sizes, int n_in,
                              void* d_out, int out_size)
{
    const float* logits = (const float*)d_in[0];  // (2,8,300,1)
    const float* boxes  = (const float*)d_in[1];  // (2,8,300,4)
    const float* masks  = (const float*)d_in[2];  // (2,8,300,96,96)
    const float* tmask  = (const float*)d_in[3];  // (2,8,96,96)
    const float* tboxes = (const float*)d_in[4];  // (2,8,4)
    const int*   tvalid = (const int*)d_in[5];    // (2,8)
    const unsigned char* vpad = (const unsigned char*)d_in[6];  // (2,96,96) bool
    float* out = (float*)d_out;                   // 600 C + 2 src + 2 tgt

    prep_all<<<BS*NF + BS, 256>>>(tmask, vpad);
    mask_heavy<<<BS*NF*NQ, 192>>>(masks);
    combine_kernel<<<(BS*NQ)/8, 256>>>(logits, boxes, tboxes, tvalid, out);
}

// round 16
// speedup vs baseline: 1.5771x; 1.5771x over previous
#include <cuda_runtime.h>
#include <math.h>

#define NQ 300
#define NF 8
#define BS 2
#define HW 96
#define HWHW 9216
#define D_TOT 73728.0f   // NF*H*W
#define L2E 1.4426950408889634f
#define LN2 0.6931471805599453f

typedef unsigned long long u64;

__device__ __forceinline__ float ex2_approx(float x) {
    float y; asm("ex2.approx.ftz.f32 %0, %1;" : "=f"(y) : "f"(x)); return y;
}
__device__ __forceinline__ float rcp_approx(float x) {
    float y; asm("rcp.approx.ftz.f32 %0, %1;" : "=f"(y) : "f"(x)); return y;
}

// Scratch (static __device__ — no allocation)
__device__ float g_focal [BS*NF*NQ];
__device__ float g_ssum  [BS*NF*NQ];
__device__ float g_stsum [BS*NF*NQ];
__device__ float g_colmax[BS*NF*NQ*HW];
__device__ float g_rowmax[BS*NF*NQ*HW];
__device__ float g_tcolmax[BS*NF*HW];
__device__ float g_trowmax[BS*NF*HW];
__device__ float g_tsum  [BS*NF];
__device__ float g_S[BS*NF*HWHW];        // per (bf,pixel): t ? -log2e : +log2e
__device__ float g_V[BS*HWHW];           // per (b,pixel): vpad ? 0 : 1
__device__ u64      g_amin[BS];          // packed (ordered-float<<32 | q)
__device__ unsigned g_cnt;

// ---------------------------------------------------------------------------
// Prep: blocks 0..BS*NF-1 (384 thr): fill S + target row/col maxes + tsum,
//       each max split across 4 partial-threads (24 elems each) for MLP.
//       blocks BS*NF.. : fill V from vpad; reset argmin scratch.
// ---------------------------------------------------------------------------
__global__ __launch_bounds__(384) void prep_all(
    const float* __restrict__ tmask, const unsigned char* __restrict__ vpad)
{
    const int tid = threadIdx.x;
    if (blockIdx.x < BS*NF) {
        const int bf = blockIdx.x;
        const float* __restrict__ T = tmask + (size_t)bf * HWHW;

        // S fill: float4, 2304 groups / 384 threads = 6 iters
        const float4* __restrict__ T4 = (const float4*)T;
        float4* __restrict__ S4 = (float4*)(g_S + (size_t)bf * HWHW);
        #pragma unroll
        for (int i = 0; i < 6; i++) {
            const int j = tid + 384*i;
            const float4 t = T4[j];
            float4 s;
            s.x = (t.x != 0.f) ? -L2E : L2E;
            s.y = (t.y != 0.f) ? -L2E : L2E;
            s.z = (t.z != 0.f) ? -L2E : L2E;
            s.w = (t.w != 0.f) ? -L2E : L2E;
            S4[j] = s;
        }

        const int idx  = tid % HW;   // column (or row) index
        const int part = tid / HW;   // 0..3 partial
        __shared__ float colp[4][HW];
        __shared__ float rowp[4][HW];
        __shared__ float rsum[4][HW];
        __shared__ float rtot[3];

        // column-max partial: rows [part*24, part*24+24)
        float cm = -1e30f;
        #pragma unroll 8
        for (int h = 0; h < 24; h++) cm = fmaxf(cm, T[(part*24 + h)*HW + idx]);
        colp[part][idx] = cm;

        // row-max + row-sum partial: cols [part*24, part*24+24), float4 loads
        float rm = -1e30f, rs = 0.f;
        const float4* R4 = (const float4*)(T + idx*HW + part*24);
        #pragma unroll
        for (int w = 0; w < 6; w++) {
            const float4 v = R4[w];
            rm = fmaxf(rm, fmaxf(fmaxf(v.x, v.y), fmaxf(v.z, v.w)));
            rs += (v.x + v.y) + (v.z + v.w);
        }
        rowp[part][idx] = rm;
        rsum[part][idx] = rs;
        __syncthreads();

        if (tid < HW) {
            g_tcolmax[bf*HW + tid] = fmaxf(fmaxf(colp[0][tid], colp[1][tid]),
                                           fmaxf(colp[2][tid], colp[3][tid]));
            g_trowmax[bf*HW + tid] = fmaxf(fmaxf(rowp[0][tid], rowp[1][tid]),
                                           fmaxf(rowp[2][tid], rowp[3][tid]));
            float r = (rsum[0][tid] + rsum[1][tid]) + (rsum[2][tid] + rsum[3][tid]);
            #pragma unroll
            for (int off = 16; off; off >>= 1)
                r += __shfl_xor_sync(0xffffffffu, r, off);
            if ((tid & 31) == 0) rtot[tid >> 5] = r;
        }
        __syncthreads();
        if (tid == 0) g_tsum[bf] = rtot[0] + rtot[1] + rtot[2];
    } else {
        const int b = blockIdx.x - BS*NF;
        const uchar4* __restrict__ VP4 = (const uchar4*)(vpad + (size_t)b * HWHW);
        float4* __restrict__ V4 = (float4*)(g_V + (size_t)b * HWHW);
        #pragma unroll
        for (int i = 0; i < 6; i++) {
            const int j = tid + 384*i;
            const uchar4 v = VP4[j];
            V4[j] = make_float4(v.x ? 0.f : 1.f, v.y ? 0.f : 1.f,
                                v.z ? 0.f : 1.f, v.w ? 0.f : 1.f);
        }
        if (tid == 0) {
            g_amin[b] = 0xFFFFFFFFFFFFFFFFULL;
            if (b == 0) g_cnt = 0u;
        }
    }
}

// ---------------------------------------------------------------------------
// Heavy kernel (R14 scalar form): one block (192 thr) per (b,f,q) tile.
// Per element: zl = x*V*S (S=±log2e); e=ex2(zl); sg=e/(1+e); G=log2(1+e)*sg^2
// Recover: focal = ln2*(0.5*f0 + 0.25*ln2*f1)
//          sum(sigmoid)=tsum+ln2*A2 ;  sum(sigmoid*t)=tsum-0.5*(A-ln2*A2)
// ---------------------------------------------------------------------------
__global__ __launch_bounds__(192) void mask_heavy(const float* __restrict__ masks)
{
    const int blk = blockIdx.x;          // ((b*NF+f)*NQ + q)
    const int bf  = blk / NQ;
    const int b   = bf / NF;
    const float4* __restrict__ X  = (const float4*)(masks + (size_t)blk * HWHW);
    const float4* __restrict__ Sp = (const float4*)(g_S   + (size_t)bf  * HWHW);
    const float4* __restrict__ Vp = (const float4*)(g_V   + (size_t)b   * HWHW);

    const int tid = threadIdx.x;
    const int c4  = tid % 24;   // float4 column
    const int r0  = tid / 24;   // 0..7 row tier

    __shared__ float rowpm[HW][24];
    __shared__ float cmS[8][HW];
    __shared__ float red[6][4];

    float f0 = 0.f, f1 = 0.f, A = 0.f, A2 = 0.f;
    float cm0 = -1e30f, cm1 = -1e30f, cm2 = -1e30f, cm3 = -1e30f;

    #pragma unroll 2
    for (int k = 0; k < 12; k++) {
        const int row = r0 + 8*k;
        const int off = row*24 + c4;             // float4 units
        const float4 x4 = __ldcs(X + off);       // streaming: masks read once
        const float4 s4 = Sp[off];               // L1/L2-resident
        const float4 v4 = Vp[off];
        float rm = -1e30f;

        {   const float xv = x4.x * v4.x;  const float zl = xv * s4.x;
            const float e  = ex2_approx(zl); const float ope = 1.f + e;
            const float u  = rcp_approx(ope);
            const float sg = e * u;        const float lg = __log2f(ope);
            const float G  = lg * sg * sg;
            f0 += G;  f1 = fmaf(s4.x, G, f1);
            A  += sg; A2 = fmaf(s4.x, sg, A2);
            rm = fmaxf(rm, xv); cm0 = fmaxf(cm0, xv); }
        {   const float xv = x4.y * v4.y;  const float zl = xv * s4.y;
            const float e  = ex2_approx(zl); const float ope = 1.f + e;
            const float u  = rcp_approx(ope);
            const float sg = e * u;        const float lg = __log2f(ope);
            const float G  = lg * sg * sg;
            f0 += G;  f1 = fmaf(s4.y, G, f1);
            A  += sg; A2 = fmaf(s4.y, sg, A2);
            rm = fmaxf(rm, xv); cm1 = fmaxf(cm1, xv); }
        {   const float xv = x4.z * v4.z;  const float zl = xv * s4.z;
            const float e  = ex2_approx(zl); const float ope = 1.f + e;
            const float u  = rcp_approx(ope);
            const float sg = e * u;        const float lg = __log2f(ope);
            const float G  = lg * sg * sg;
            f0 += G;  f1 = fmaf(s4.z, G, f1);
            A  += sg; A2 = fmaf(s4.z, sg, A2);
            rm = fmaxf(rm, xv); cm2 = fmaxf(cm2, xv); }
        {   const float xv = x4.w * v4.w;  const float zl = xv * s4.w;
            const float e  = ex2_approx(zl); const float ope = 1.f + e;
            const float u  = rcp_approx(ope);
            const float sg = e * u;        const float lg = __log2f(ope);
            const float G  = lg * sg * sg;
            f0 += G;  f1 = fmaf(s4.w, G, f1);
            A  += sg; A2 = fmaf(s4.w, sg, A2);
            rm = fmaxf(rm, xv); cm3 = fmaxf(cm3, xv); }

        rowpm[row][c4] = rm;
    }

    *(float4*)&cmS[r0][4*c4] = make_float4(cm0, cm1, cm2, cm3);

    const int lane = tid & 31, warp = tid >> 5;
    #pragma unroll
    for (int off = 16; off; off >>= 1) {
        f0 += __shfl_xor_sync(0xffffffffu, f0, off);
        f1 += __shfl_xor_sync(0xffffffffu, f1, off);
        A  += __shfl_xor_sync(0xffffffffu, A,  off);
        A2 += __shfl_xor_sync(0xffffffffu, A2, off);
    }
    if (lane == 0) { red[warp][0] = f0; red[warp][1] = f1; red[warp][2] = A; red[warp][3] = A2; }
    __syncthreads();

    if (tid == 0) {
        float F0 = 0.f, F1 = 0.f, At = 0.f, A2t = 0.f;
        #pragma unroll
        for (int i = 0; i < 6; i++) {
            F0 += red[i][0]; F1 += red[i][1]; At += red[i][2]; A2t += red[i][3];
        }
        const float ts = g_tsum[bf];
        g_focal[blk] = LN2 * (0.5f*F0 + 0.25f*LN2*F1);
        g_ssum [blk] = ts + LN2*A2t;
        g_stsum[blk] = ts - 0.5f*(At - LN2*A2t);
    }
    if (tid < HW) {
        const float4* rp = (const float4*)rowpm[tid];
        float4 a = rp[0];
        #pragma unroll
        for (int i = 1; i < 6; i++) {
            const float4 v = rp[i];
            a.x = fmaxf(a.x, v.x); a.y = fmaxf(a.y, v.y);
            a.z = fmaxf(a.z, v.z); a.w = fmaxf(a.w, v.w);
        }
        g_rowmax[(size_t)blk*HW + tid] = fmaxf(fmaxf(a.x, a.y), fmaxf(a.z, a.w));
    } else {
        const int col = tid - HW;
        float m = cmS[0][col];
        #pragma unroll
        for (int i = 1; i < 8; i++) m = fmaxf(m, cmS[i][col]);
        g_colmax[(size_t)blk*HW + col] = m;
    }
}

// ---------------------------------------------------------------------------
// Combine: one WARP per (b,q), fused argmin via packed atomicMin.
// grid = 75 blocks x 8 warps = 600 warps exactly.
// ---------------------------------------------------------------------------
__global__ __launch_bounds__(256) void combine_kernel(
    const float* __restrict__ logits, const float* __restrict__ boxes,
    const float* __restrict__ tboxes, const int* __restrict__ tvalid,
    float* __restrict__ out)
{
    const int bq = blockIdx.x * 8 + (threadIdx.x >> 5);
    const int b  = bq / NQ;
    const int q  = bq % NQ;
    const int lane = threadIdx.x & 31;

    float v0 = 0.f, v1 = 0.f, v2 = 0.f, v3 = 0.f, v4 = 0.f, v5 = 0.f;
    #pragma unroll
    for (int j = lane; j < NF*HW; j += 32) {
        const int f = j / HW, k = j % HW;
        const int src  = ((b*NF + f)*NQ + q)*HW + k;
        const int tsrc = (b*NF + f)*HW + k;
        const float ym = g_colmax[src];
        const float ty = g_tcolmax[tsrc];
        const float sy = rcp_approx(1.f + ex2_approx(-L2E*ym));
        v0 += sy; v1 += (ty != 0.f) ? sy : 0.f; v2 += ty;
        const float xm = g_rowmax[src];
        const float tx = g_trowmax[tsrc];
        const float sx = rcp_approx(1.f + ex2_approx(-L2E*xm));
        v3 += sx; v4 += (tx != 0.f) ? sx : 0.f; v5 += tx;
    }

    float cls = 0.f, wv = 0.f, cb = 0.f, cg = 0.f;
    float focal = 0.f, ss = 0.f, st = 0.f, ts = 0.f;
    if (lane < NF) {
        const int f  = lane;
        const int idx = (b*NF + f)*NQ + q;
        focal = g_focal[idx]; ss = g_ssum[idx]; st = g_stsum[idx];
        ts = g_tsum[b*NF + f];

        const float lg = logits[idx];
        const float p  = __fdividef(1.f, 1.f + __expf(-lg));
        const float neg = 0.75f * p * p * (-__logf(1.f - p + 1e-8f));
        const float pos = 0.25f * (1.f - p) * (1.f - p) * (-__logf(p + 1e-8f));
        wv = (tvalid[b*NF + f] != 0) ? 1.f : 0.f;
        cls = wv * (pos - neg);

        const float* sb = boxes  + (size_t)idx * 4;
        const float* tb = tboxes + (size_t)(b*NF + f) * 4;
        cb = fabsf(sb[0]-tb[0]) + fabsf(sb[1]-tb[1])
           + fabsf(sb[2]-tb[2]) + fabsf(sb[3]-tb[3]);

        const float sx0 = sb[0] - 0.5f*sb[2], sy0 = sb[1] - 0.5f*sb[3];
        const float sx1 = sb[0] + 0.5f*sb[2], sy1 = sb[1] + 0.5f*sb[3];
        const float tx0 = tb[0] - 0.5f*tb[2], ty0 = tb[1] - 0.5f*tb[3];
        const float tx1 = tb[0] + 0.5f*tb[2], ty1 = tb[1] + 0.5f*tb[3];
        const float a1 = (sx1 - sx0) * (sy1 - sy0);
        const float a2 = (tx1 - tx0) * (ty1 - ty0);
        float iw = fminf(sx1, tx1) - fmaxf(sx0, tx0); iw = fmaxf(iw, 0.f);
        float ih = fminf(sy1, ty1) - fmaxf(sy0, ty0); ih = fmaxf(ih, 0.f);
        const float inter = iw * ih;
        const float uni = a1 + a2 - inter;
        const float iou = inter / uni;
        float cw = fmaxf(sx1, tx1) - fminf(sx0, tx0); cw = fmaxf(cw, 0.f);
        float ch = fmaxf(sy1, ty1) - fminf(sy0, ty0); ch = fmaxf(ch, 0.f);
        const float areac = cw * ch;
        cg = -(iou - (areac - uni) / areac);
    }

    #pragma unroll
    for (int off = 16; off; off >>= 1) {
        v0 += __shfl_xor_sync(0xffffffffu, v0, off);
        v1 += __shfl_xor_sync(0xffffffffu, v1, off);
        v2 += __shfl_xor_sync(0xffffffffu, v2, off);
        v3 += __shfl_xor_sync(0xffffffffu, v3, off);
        v4 += __shfl_xor_sync(0xffffffffu, v4, off);
        v5 += __shfl_xor_sync(0xffffffffu, v5, off);
        cls += __shfl_xor_sync(0xffffffffu, cls, off);
        wv  += __shfl_xor_sync(0xffffffffu, wv,  off);
        cb  += __shfl_xor_sync(0xffffffffu, cb,  off);
        cg  += __shfl_xor_sync(0xffffffffu, cg,  off);
        focal += __shfl_xor_sync(0xffffffffu, focal, off);
        ss  += __shfl_xor_sync(0xffffffffu, ss,  off);
        st  += __shfl_xor_sync(0xffffffffu, st,  off);
        ts  += __shfl_xor_sync(0xffffffffu, ts,  off);
    }

    if (lane == 0) {
        const float cost_mask = focal / D_TOT;
        const float cost_dice = -(2.f*st + 1.f) / (ss + ts + 1.f);
        const float dice_y = (2.f*v1 + 1.f) / (v0 + v2 + 1.f);
        const float dice_x = (2.f*v4 + 1.f) / (v3 + v5 + 1.f);
        const float cost_proj = -0.5f * (dice_y + dice_x);
        const float c = cls / wv + cb * (1.f/(float)NF) + cg * (1.f/(float)NF)
                      + cost_mask + cost_dice + cost_proj;
        out[bq] = c;

        // fused argmin: total-order key (ordered-float, then q for first-occurrence)
        unsigned ub = __float_as_uint(c);
        ub = (ub & 0x80000000u) ? ~ub : (ub | 0x80000000u);
        const u64 key = ((u64)ub << 32) | (unsigned)q;
        atomicMin(&g_amin[b], key);
        __threadfence();
        const unsigned prev = atomicAdd(&g_cnt, 1u);
        if (prev == BS*NQ - 1) {   // last warp: publish indices
            #pragma unroll
            for (int bb = 0; bb < BS; bb++) {
                const u64 k = atomicMin(&g_amin[bb], 0xFFFFFFFFFFFFFFFFULL); // no-op read
                out[BS*NQ + bb]      = (float)(unsigned)(k & 0xFFFFFFFFu);
                out[BS*NQ + BS + bb] = 0.f;
            }
        }
    }
}

extern "C" void kernel_launch(void* const* d_in, const int* in_sizes, int n_in,
                              void* d_out, int out_size)
{
    const float* logits = (const float*)d_in[0];  // (2,8,300,1)
    const float* boxes  = (const float*)d_in[1];  // (2,8,300,4)
    const float* masks  = (const float*)d_in[2];  // (2,8,300,96,96)
    const float* tmask  = (const float*)d_in[3];  // (2,8,96,96)
    const float* tboxes = (const float*)d_in[4];  // (2,8,4)
    const int*   tvalid = (const int*)d_in[5];    // (2,8)
    const unsigned char* vpad = (const unsigned char*)d_in[6];  // (2,96,96) bool
    float* out = (float*)d_out;                   // 600 C + 2 src + 2 tgt

    prep_all<<<BS*NF + BS, 384>>>(tmask, vpad);
    mask_heavy<<<BS*NF*NQ, 192>>>(masks);
    combine_kernel<<<(BS*NQ)/8, 256>>>(logits, boxes, tboxes, tvalid, out);
}